// round 13
// baseline (speedup 1.0000x reference)
#include <cuda_runtime.h>
#include <math.h>

#define N_NODES 512
#define TDIM 288
#define LDIM 128
#define BBATCH 4
#define MROWS (BBATCH * N_NODES)   // 2048

typedef unsigned long long u64;
typedef unsigned int u32;

// ---- packed f32x2 helpers (sm_100+) ----
__device__ __forceinline__ u64 add2(u64 a, u64 b) {
    u64 r; asm("add.rn.f32x2 %0,%1,%2;" : "=l"(r) : "l"(a), "l"(b)); return r;
}
__device__ __forceinline__ u64 fma2(u64 a, u64 b, u64 c) {
    u64 r; asm("fma.rn.f32x2 %0,%1,%2,%3;" : "=l"(r) : "l"(a), "l"(b), "l"(c)); return r;
}
__device__ __forceinline__ float lo32(u64 v) { return __uint_as_float((unsigned)(v & 0xffffffffu)); }
__device__ __forceinline__ float hi32(u64 v) { return __uint_as_float((unsigned)(v >> 32)); }
__device__ __forceinline__ u64 pack2(float x, float y) {
    return ((u64)__float_as_uint(y) << 32) | (u64)__float_as_uint(x);
}

// ---- tf32 helpers ----
__device__ __forceinline__ u32 tf32_bits(float v) {
    u32 r; asm("cvt.rna.tf32.f32 %0,%1;" : "=r"(r) : "f"(v));
    return r;
}
__device__ __forceinline__ void mma_tf32(float* d, const u32* a, const u32* b) {
    asm("mma.sync.aligned.m16n8k8.row.col.f32.tf32.tf32.f32 "
        "{%0,%1,%2,%3}, {%4,%5,%6,%7}, {%8,%9}, {%0,%1,%2,%3};"
        : "+f"(d[0]), "+f"(d[1]), "+f"(d[2]), "+f"(d[3])
        : "r"(a[0]), "r"(a[1]), "r"(a[2]), "r"(a[3]), "r"(b[0]), "r"(b[1]));
}

// ---- cp.async helpers ----
__device__ __forceinline__ void cpa16(u32 s, const void* g) {
    asm volatile("cp.async.ca.shared.global [%0], [%1], 16;" :: "r"(s), "l"(g));
}
__device__ __forceinline__ void cp_commit() {
    asm volatile("cp.async.commit_group;");
}
template <int N> __device__ __forceinline__ void cp_wait() {
    asm volatile("cp.async.wait_group %0;" :: "n"(N));
}

// Scratch (device globals)
__device__ float g_X1[MROWS * LDIM];
__device__ float g_X2[MROWS * LDIM];
__device__ float g_S1[MROWS * LDIM];
__device__ float g_S2P[MROWS * LDIM];
__device__ float g_P[BBATCH * N_NODES * N_NODES];

// ---------------------------------------------------------------------------
// GEMM core: BM=32, BN=64, BK=32, 8 warps (2m x 4n), 4-stage cp.async ring
// over RAW fp32 tiles; tf32 hi/lo split done in registers at fragment load.
// ---------------------------------------------------------------------------
#define SROW 36                     // fp32 per smem row (32 + 4 pad; 144B, 16B-aligned)
#define ST_A (32 * SROW)            // 1152 floats
#define ST_B (64 * SROW)            // 2304 floats
#define ST_SZ (ST_A + ST_B)         // 3456 floats per stage
#define NSTAGE 4
#define GEMM_SMEM_FLOATS (NSTAGE * ST_SZ)   // 13824 floats = 55296 B

// Split one fp32 fragment value into tf32 hi/lo bit patterns.
__device__ __forceinline__ void split1(float v, u32& h, u32& l) {
    h = tf32_bits(v);
    l = tf32_bits(v - __uint_as_float(h));
}

// mma over one 32-K chunk: read fp32 frags from smem, convert, 3xTF32 mma.
__device__ __forceinline__ void mma_chunk_cvt(float acc[2][4],
                                              const float* SA, const float* SB,
                                              int wm, int wn, int gid, int ctid) {
    const int ar0 = (wm * 16 + gid) * SROW;
    const int ar1 = (wm * 16 + gid + 8) * SROW;
#pragma unroll
    for (int kk = 0; kk < 4; kk++) {
        int k8 = kk * 8;
        float av[4], bv[2][2];
        av[0] = SA[ar0 + k8 + ctid];
        av[1] = SA[ar1 + k8 + ctid];
        av[2] = SA[ar0 + k8 + ctid + 4];
        av[3] = SA[ar1 + k8 + ctid + 4];
#pragma unroll
        for (int nf = 0; nf < 2; nf++) {
            int r = (wn * 16 + nf * 8 + gid) * SROW;
            bv[nf][0] = SB[r + k8 + ctid];
            bv[nf][1] = SB[r + k8 + ctid + 4];
        }
        u32 ah[4], al[4], bh[2][2], bl[2][2];
#pragma unroll
        for (int i = 0; i < 4; i++) split1(av[i], ah[i], al[i]);
#pragma unroll
        for (int nf = 0; nf < 2; nf++) {
            split1(bv[nf][0], bh[nf][0], bl[nf][0]);
            split1(bv[nf][1], bh[nf][1], bl[nf][1]);
        }
#pragma unroll
        for (int nf = 0; nf < 2; nf++) {
            mma_tf32(acc[nf], ah, bh[nf]);
            mma_tf32(acc[nf], ah, bl[nf]);
            mma_tf32(acc[nf], al, bh[nf]);
        }
    }
}

// Stage 1: [X1|X2] = leaky(x @ [W1;W2]^T + bias). grid (64, 4).
__global__ __launch_bounds__(256)
void stage1_mma(const float* __restrict__ x,
                const float* __restrict__ W1, const float* __restrict__ W2,
                const float* __restrict__ b1, const float* __restrict__ b2,
                float* __restrict__ X1, float* __restrict__ X2)
{
    extern __shared__ __align__(16) float gsm[];
    const u32 sb = (u32)__cvta_generic_to_shared(gsm);

    const int t = threadIdx.x;
    const int lane = t & 31, warp = t >> 5;
    const int wm = warp >> 2, wn = warp & 3;
    const int gid = lane >> 2, ctid = lane & 3;
    const int m0 = blockIdx.x * 32;
    const int n0 = blockIdx.y * 64;

    // loader mapping: A 256 f4 (1/thread), B 512 f4 (2/thread)
    const int arI = t >> 3, ak = (t & 7) * 4;        // A row, k
    const int brI = t >> 3, bk = (t & 7) * 4;        // B rows brI and brI+32
    const float* aG  = x + (size_t)(m0 + arI) * TDIM + ak;
    const int bn1 = n0 + brI, bn2 = n0 + brI + 32;
    const float* bG1 = (bn1 < 128) ? W1 + (size_t)bn1 * TDIM + bk
                                   : W2 + (size_t)(bn1 - 128) * TDIM + bk;
    const float* bG2 = (bn2 < 128) ? W1 + (size_t)bn2 * TDIM + bk
                                   : W2 + (size_t)(bn2 - 128) * TDIM + bk;
    const u32 sA  = sb + (arI * SROW + ak) * 4;
    const u32 sB1 = sb + (ST_A + brI * SROW + bk) * 4;
    const u32 sB2 = sb + (ST_A + (brI + 32) * SROW + bk) * 4;

    float acc[2][4] = {};
    const int nt = TDIM / 32;   // 9

#define S1_ISSUE(ch) do {                                  \
        int kc_ = (ch) * 32;                               \
        u32 so_ = (u32)(((ch) & 3) * ST_SZ * 4);           \
        cpa16(sA  + so_, aG  + kc_);                       \
        cpa16(sB1 + so_, bG1 + kc_);                       \
        cpa16(sB2 + so_, bG2 + kc_);                       \
        cp_commit();                                       \
    } while (0)

    S1_ISSUE(0); S1_ISSUE(1); S1_ISSUE(2);
    for (int ti = 0; ti < nt; ti++) {
        cp_wait<2>();
        __syncthreads();
        if (ti + 3 < nt) S1_ISSUE(ti + 3);
        const float* stg = gsm + (ti & 3) * ST_SZ;
        mma_chunk_cvt(acc, stg, stg + ST_A, wm, wn, gid, ctid);
        __syncthreads();
    }
#undef S1_ISSUE

    const int half = (n0 < 128);
    float* OUT = half ? X1 : X2;
    const float* bias = half ? b1 : b2;
    const int nloc0 = half ? n0 : n0 - 128;
    const int row = m0 + wm * 16 + gid;
#pragma unroll
    for (int nf = 0; nf < 2; nf++) {
        int col = nloc0 + wn * 16 + nf * 8 + 2 * ctid;
        float v0 = acc[nf][0] + bias[col];
        float v1 = acc[nf][1] + bias[col + 1];
        float v2 = acc[nf][2] + bias[col];
        float v3 = acc[nf][3] + bias[col + 1];
        v0 = fmaxf(v0, 0.2f * v0); v1 = fmaxf(v1, 0.2f * v1);
        v2 = fmaxf(v2, 0.2f * v2); v3 = fmaxf(v3, 0.2f * v3);
        *(float2*)&OUT[(size_t)row * LDIM + col]       = make_float2(v0, v1);
        *(float2*)&OUT[(size_t)(row + 8) * LDIM + col] = make_float2(v2, v3);
    }
}

// Stage 2: z=0: S1 = X1 @ Wp_a^T ; z=1: S2P = X2 @ Wp_b^T + bp. grid (64,2,2).
__global__ __launch_bounds__(256)
void stage2_mma(const float* __restrict__ X1, const float* __restrict__ X2,
                const float* __restrict__ Wp, const float* __restrict__ bp,
                float* __restrict__ S1, float* __restrict__ S2P)
{
    extern __shared__ __align__(16) float gsm[];
    const u32 sb = (u32)__cvta_generic_to_shared(gsm);

    const int t = threadIdx.x;
    const int lane = t & 31, warp = t >> 5;
    const int wm = warp >> 2, wn = warp & 3;
    const int gid = lane >> 2, ctid = lane & 3;
    const int m0 = blockIdx.x * 32;
    const int n0 = blockIdx.y * 64;
    const int z  = blockIdx.z;

    const float* A = z ? X2 : X1;
    const int arI = t >> 3, ak = (t & 7) * 4;
    const int brI = t >> 3, bk = (t & 7) * 4;
    const float* aG  = A + (size_t)(m0 + arI) * LDIM + ak;
    const float* bG1 = Wp + (size_t)(n0 + brI) * (2 * LDIM) + z * LDIM + bk;
    const float* bG2 = Wp + (size_t)(n0 + brI + 32) * (2 * LDIM) + z * LDIM + bk;
    const u32 sA  = sb + (arI * SROW + ak) * 4;
    const u32 sB1 = sb + (ST_A + brI * SROW + bk) * 4;
    const u32 sB2 = sb + (ST_A + (brI + 32) * SROW + bk) * 4;

    float acc[2][4] = {};
    const int nt = LDIM / 32;   // 4

#define S2_ISSUE(ch) do {                                  \
        int kc_ = (ch) * 32;                               \
        u32 so_ = (u32)(((ch) & 3) * ST_SZ * 4);           \
        cpa16(sA  + so_, aG  + kc_);                       \
        cpa16(sB1 + so_, bG1 + kc_);                       \
        cpa16(sB2 + so_, bG2 + kc_);                       \
        cp_commit();                                       \
    } while (0)

    S2_ISSUE(0); S2_ISSUE(1); S2_ISSUE(2);
    for (int ti = 0; ti < nt; ti++) {
        cp_wait<2>();
        __syncthreads();
        if (ti + 3 < nt) S2_ISSUE(ti + 3);
        const float* stg = gsm + (ti & 3) * ST_SZ;
        mma_chunk_cvt(acc, stg, stg + ST_A, wm, wn, gid, ctid);
        __syncthreads();
    }
#undef S2_ISSUE

    float* OUT = z ? S2P : S1;
    const int row = m0 + wm * 16 + gid;
#pragma unroll
    for (int nf = 0; nf < 2; nf++) {
        int col = n0 + wn * 16 + nf * 8 + 2 * ctid;
        float bv0 = z ? bp[col] : 0.f;
        float bv1 = z ? bp[col + 1] : 0.f;
        *(float2*)&OUT[(size_t)row * LDIM + col]       = make_float2(acc[nf][0] + bv0, acc[nf][1] + bv1);
        *(float2*)&OUT[(size_t)(row + 8) * LDIM + col] = make_float2(acc[nf][2] + bv0, acc[nf][3] + bv1);
    }
}

// ---------------------------------------------------------------------------
// Pairwise: 64x64 tile per block (one b), grid (8, 8, 4), 128 threads.
// 4x8 u64 micro-tile per thread (R12 — proven).
// ---------------------------------------------------------------------------
#define SR2 65   // u64 per row (64 + 1 pad)
#define PW_S2   (64 * SR2)          // 4160
#define PW_C1   (2 * 64 * SR2)      // 8320
#define PW_C2   (PW_C1 + 64)        // 8384
#define PW_ROWF ((PW_C2 + 64) * 2)  // float index of rowA = 16896
#define PW_U64_TOTAL (PW_C2 + 64 + 64)  // 8512 u64 = 68,096 bytes

__global__ __launch_bounds__(128)
void pairwise_kernel(const float* __restrict__ S1, const float* __restrict__ S2P,
                     const float* __restrict__ Wb, const float* __restrict__ bb,
                     float* __restrict__ P)
{
    extern __shared__ __align__(16) u64 sm[];
    u64*   s1t  = sm;
    u64*   s2t  = sm + PW_S2;
    u64*   c1   = sm + PW_C1;
    u64*   c2   = sm + PW_C2;
    float* rowA = ((float*)sm) + PW_ROWF;        // [64]
    float* rowB = rowA + 64;                     // [64]

    const int t  = threadIdx.x;
    const int tx = t & 7;           // j micro col 0..7
    const int ty = t >> 3;          // i micro row 0..15
    const int j0 = blockIdx.x * 64;
    const int i0 = blockIdx.y * 64;
    const int b  = blockIdx.z;

    if (t < 64) {
        float2 w = ((const float2*)Wb)[t];
        c1[t] = pack2(0.6f * w.x, 0.6f * w.y);
        c2[t] = pack2(0.4f * w.x, 0.4f * w.y);
    }

    const float4* S1v = (const float4*)(S1  + ((size_t)b * N_NODES + i0) * LDIM);
    const float4* S2v = (const float4*)(S2P + ((size_t)b * N_NODES + j0) * LDIM);
#pragma unroll
    for (int s = 0; s < 16; s++) {
        int f   = t + s * 128;          // 0..2047
        int row = f >> 5;
        int c4  = f & 31;
        float4 v = S1v[row * 32 + c4];
        float4 w = S2v[row * 32 + c4];
        float2* d = (float2*)&s1t[row * SR2 + c4 * 2];
        d[0] = make_float2(v.x, v.y);
        d[1] = make_float2(v.z, v.w);
        float2* e = (float2*)&s2t[row * SR2 + c4 * 2];
        e[0] = make_float2(w.x, w.y);
        e[1] = make_float2(w.z, w.w);
    }
    __syncthreads();

    // separable linear parts: 2 threads per row, both arrays
    {
        int row  = t >> 1;
        int half = t & 1;
        const u64* cc = c1 + half * 32;
        const u64* srcA = s1t + row * SR2 + half * 32;
        const u64* srcB = s2t + row * SR2 + half * 32;
        u64 a0 = 0, a1 = 0, b0 = 0, b1 = 0;
#pragma unroll
        for (int q = 0; q < 32; q += 2) {
            a0 = fma2(cc[q],     srcA[q],     a0);
            a1 = fma2(cc[q + 1], srcA[q + 1], a1);
            b0 = fma2(cc[q],     srcB[q],     b0);
            b1 = fma2(cc[q + 1], srcB[q + 1], b1);
        }
        float sa = lo32(a0) + hi32(a0) + lo32(a1) + hi32(a1);
        float sb = lo32(b0) + hi32(b0) + lo32(b1) + hi32(b1);
        sa += __shfl_xor_sync(0xffffffffu, sa, 1);
        sb += __shfl_xor_sync(0xffffffffu, sb, 1);
        if (half == 0) { rowA[row] = sa; rowB[row] = sb; }
    }
    __syncthreads();

    u64 acc[4][8] = {};
    const u64 MASK = 0x7fffffff7fffffffULL;
#pragma unroll 2
    for (int kk = 0; kk < 64; kk++) {
        u64 cw = c2[kk];
        u64 ra[4], rb[8];
#pragma unroll
        for (int r = 0; r < 4; r++) ra[r] = s1t[(ty + 16 * r) * SR2 + kk];
#pragma unroll
        for (int c = 0; c < 8; c++) rb[c] = s2t[(tx + 8 * c) * SR2 + kk];
#pragma unroll
        for (int r = 0; r < 4; r++)
#pragma unroll
            for (int c = 0; c < 8; c++) {
                u64 v = add2(ra[r], rb[c]);
                acc[r][c] = fma2(cw, v & MASK, acc[r][c]);
            }
    }

    const float bbv = bb[0];
    float* Pb = P + (size_t)b * N_NODES * N_NODES;
#pragma unroll
    for (int r = 0; r < 4; r++) {
        int i = i0 + ty + 16 * r;
        float ai = rowA[ty + 16 * r] + bbv;
#pragma unroll
        for (int c = 0; c < 8; c++) {
            int j = j0 + tx + 8 * c;
            float z = lo32(acc[r][c]) + hi32(acc[r][c])
                    + ai + rowB[tx + 8 * c];
            Pb[(size_t)i * N_NODES + j] = 1.f / (1.f + __expf(-z));
        }
    }
}

// ---------------------------------------------------------------------------
// Finalize: p = mean_b P -> diag mask -> clamped logit -> +logistic(noise)
//           -> sigmoid(/0.2). One float4 per thread.
// ---------------------------------------------------------------------------
__global__ __launch_bounds__(128)
void finalize_kernel(const float* __restrict__ P, const float* __restrict__ noise,
                     float* __restrict__ out)
{
    int q = blockIdx.x * 128 + threadIdx.x;   // float4 index
    const int PL4 = N_NODES * N_NODES / 4;
    float4 p0 = ((const float4*)P)[q];
    float4 p1 = ((const float4*)P)[q + PL4];
    float4 p2 = ((const float4*)P)[q + 2 * PL4];
    float4 p3 = ((const float4*)P)[q + 3 * PL4];
    float4 ns = ((const float4*)noise)[q];

    int idx0 = q * 4;
    int i = idx0 >> 9;
    int jbase = idx0 & (N_NODES - 1);

    float pv[4] = { 0.25f * (p0.x + p1.x + p2.x + p3.x),
                    0.25f * (p0.y + p1.y + p2.y + p3.y),
                    0.25f * (p0.z + p1.z + p2.z + p3.z),
                    0.25f * (p0.w + p1.w + p2.w + p3.w) };
    float nv[4] = { ns.x, ns.y, ns.z, ns.w };
    float4 o;
    float* op = (float*)&o;
#pragma unroll
    for (int e = 0; e < 4; e++) {
        float p = pv[e];
        if (i == jbase + e) p = 0.f;
        float lp = __logf(p + 1e-10f) - __logf(1.0f + (1e-10f - p));
        lp = fminf(fmaxf(lp, -10.f), 10.f);
        float lo = __logf(nv[e]) - __logf(1.0f - nv[e]);
        float z = (lp + lo) * 5.0f;     // / TEMPERATURE (0.2)
        op[e] = 1.f / (1.f + __expf(-z));
    }
    ((float4*)out)[q] = o;
}

// ---------------------------------------------------------------------------
extern "C" void kernel_launch(void* const* d_in, const int* in_sizes, int n_in,
                              void* d_out, int out_size)
{
    const float* x     = (const float*)d_in[0];
    const float* W1    = (const float*)d_in[1];
    const float* b1    = (const float*)d_in[2];
    const float* W2    = (const float*)d_in[3];
    const float* b2    = (const float*)d_in[4];
    const float* Wp    = (const float*)d_in[5];
    const float* bp    = (const float*)d_in[6];
    const float* Wb    = (const float*)d_in[7];
    const float* bb    = (const float*)d_in[8];
    const float* noise = (const float*)d_in[9];
    float* out = (float*)d_out;

    float *X1, *X2, *S1, *S2P, *P;
    cudaGetSymbolAddress((void**)&X1,  g_X1);
    cudaGetSymbolAddress((void**)&X2,  g_X2);
    cudaGetSymbolAddress((void**)&S1,  g_S1);
    cudaGetSymbolAddress((void**)&S2P, g_S2P);
    cudaGetSymbolAddress((void**)&P,   g_P);

    const size_t gemm_smem = (size_t)GEMM_SMEM_FLOATS * sizeof(float);  // 55296 B
    cudaFuncSetAttribute(stage1_mma, cudaFuncAttributeMaxDynamicSharedMemorySize,
                         (int)gemm_smem);
    cudaFuncSetAttribute(stage2_mma, cudaFuncAttributeMaxDynamicSharedMemorySize,
                         (int)gemm_smem);

    // Stage 1: [X1|X2] = leaky(x @ [W1;W2]^T + bias)
    stage1_mma<<<dim3(MROWS / 32, 4), 256, gemm_smem>>>(x, W1, W2, b1, b2, X1, X2);

    // Stage 2: S1 = X1@Wp_a^T, S2P = X2@Wp_b^T + bp
    stage2_mma<<<dim3(MROWS / 32, 2, 2), 256, gemm_smem>>>(X1, X2, Wp, bp, S1, S2P);

    // Stage 3: pairwise sigmoid planes (64x64 tiles, one b per block)
    size_t pw_smem = (size_t)PW_U64_TOTAL * sizeof(u64);   // 68,096 B
    cudaFuncSetAttribute(pairwise_kernel,
                         cudaFuncAttributeMaxDynamicSharedMemorySize, (int)pw_smem);
    dim3 g3(N_NODES / 64, N_NODES / 64, BBATCH);   // 8 x 8 x 4 = 256
    pairwise_kernel<<<g3, dim3(128), pw_smem>>>(S1, S2P, Wb, bb, P);

    // Stage 4: epilogue
    finalize_kernel<<<N_NODES * N_NODES / 4 / 128, 128>>>(P, noise, out);
}

// round 14
// speedup vs baseline: 1.0302x; 1.0302x over previous
#include <cuda_runtime.h>
#include <math.h>

#define N_NODES 512
#define TDIM 288
#define LDIM 128
#define BBATCH 4
#define MROWS (BBATCH * N_NODES)   // 2048

typedef unsigned long long u64;
typedef unsigned int u32;

// ---- packed f32x2 helpers (sm_100+) ----
__device__ __forceinline__ u64 add2(u64 a, u64 b) {
    u64 r; asm("add.rn.f32x2 %0,%1,%2;" : "=l"(r) : "l"(a), "l"(b)); return r;
}
__device__ __forceinline__ u64 fma2(u64 a, u64 b, u64 c) {
    u64 r; asm("fma.rn.f32x2 %0,%1,%2,%3;" : "=l"(r) : "l"(a), "l"(b), "l"(c)); return r;
}
__device__ __forceinline__ float lo32(u64 v) { return __uint_as_float((unsigned)(v & 0xffffffffu)); }
__device__ __forceinline__ float hi32(u64 v) { return __uint_as_float((unsigned)(v >> 32)); }
__device__ __forceinline__ u64 pack2(float x, float y) {
    return ((u64)__float_as_uint(y) << 32) | (u64)__float_as_uint(x);
}

// ---- tf32 helpers ----
__device__ __forceinline__ u32 tf32_bits(float v) {
    u32 r; asm("cvt.rna.tf32.f32 %0,%1;" : "=r"(r) : "f"(v));
    return r;
}
__device__ __forceinline__ void mma_tf32(float* d, const u32* a, const u32* b) {
    asm("mma.sync.aligned.m16n8k8.row.col.f32.tf32.tf32.f32 "
        "{%0,%1,%2,%3}, {%4,%5,%6,%7}, {%8,%9}, {%0,%1,%2,%3};"
        : "+f"(d[0]), "+f"(d[1]), "+f"(d[2]), "+f"(d[3])
        : "r"(a[0]), "r"(a[1]), "r"(a[2]), "r"(a[3]), "r"(b[0]), "r"(b[1]));
}

// ---- cp.async helpers ----
__device__ __forceinline__ void cpa16(u32 s, const void* g) {
    asm volatile("cp.async.ca.shared.global [%0], [%1], 16;" :: "r"(s), "l"(g));
}
__device__ __forceinline__ void cp_commit() {
    asm volatile("cp.async.commit_group;");
}
template <int N> __device__ __forceinline__ void cp_wait() {
    asm volatile("cp.async.wait_group %0;" :: "n"(N));
}

// Scratch (device globals)
__device__ float g_X1[MROWS * LDIM];
__device__ float g_X2[MROWS * LDIM];
__device__ float g_S1[MROWS * LDIM];
__device__ float g_S2P[MROWS * LDIM];
__device__ float g_P[BBATCH * N_NODES * N_NODES];

// ---------------------------------------------------------------------------
// GEMM core: BM=32, BN=64, BK=32, 8 warps (2m x 4n), 4-stage cp.async ring,
// tf32 split in registers. THREE independent accumulator sets (hh/hl/lh)
// so the 3 mma per step have no RAW chain; summed in epilogue.
// ---------------------------------------------------------------------------
#define SROW 36
#define ST_A (32 * SROW)
#define ST_B (64 * SROW)
#define ST_SZ (ST_A + ST_B)
#define NSTAGE 4
#define GEMM_SMEM_FLOATS (NSTAGE * ST_SZ)   // 55296 B

__device__ __forceinline__ void split1(float v, u32& h, u32& l) {
    h = tf32_bits(v);
    l = tf32_bits(v - __uint_as_float(h));
}

struct Acc3 {
    float hh[2][4], hl[2][4], lh[2][4];
    __device__ __forceinline__ void zero() {
#pragma unroll
        for (int nf = 0; nf < 2; nf++)
#pragma unroll
            for (int e = 0; e < 4; e++) {
                hh[nf][e] = 0.f; hl[nf][e] = 0.f; lh[nf][e] = 0.f;
            }
    }
    __device__ __forceinline__ float get(int nf, int e) const {
        return hh[nf][e] + (hl[nf][e] + lh[nf][e]);
    }
};

__device__ __forceinline__ void mma_chunk_cvt(Acc3& A3,
                                              const float* SA, const float* SB,
                                              int wm, int wn, int gid, int ctid) {
    const int ar0 = (wm * 16 + gid) * SROW;
    const int ar1 = (wm * 16 + gid + 8) * SROW;
#pragma unroll
    for (int kk = 0; kk < 4; kk++) {
        int k8 = kk * 8;
        float av[4], bv[2][2];
        av[0] = SA[ar0 + k8 + ctid];
        av[1] = SA[ar1 + k8 + ctid];
        av[2] = SA[ar0 + k8 + ctid + 4];
        av[3] = SA[ar1 + k8 + ctid + 4];
#pragma unroll
        for (int nf = 0; nf < 2; nf++) {
            int r = (wn * 16 + nf * 8 + gid) * SROW;
            bv[nf][0] = SB[r + k8 + ctid];
            bv[nf][1] = SB[r + k8 + ctid + 4];
        }
        u32 ah[4], al[4], bh[2][2], bl[2][2];
#pragma unroll
        for (int i = 0; i < 4; i++) split1(av[i], ah[i], al[i]);
#pragma unroll
        for (int nf = 0; nf < 2; nf++) {
            split1(bv[nf][0], bh[nf][0], bl[nf][0]);
            split1(bv[nf][1], bh[nf][1], bl[nf][1]);
        }
#pragma unroll
        for (int nf = 0; nf < 2; nf++) {
            mma_tf32(A3.hh[nf], ah, bh[nf]);   // independent accs -> no RAW chain
            mma_tf32(A3.hl[nf], ah, bl[nf]);
            mma_tf32(A3.lh[nf], al, bh[nf]);
        }
    }
}

// Stage 1: [X1|X2] = leaky(x @ [W1;W2]^T + bias). grid (64, 4).
__global__ __launch_bounds__(256)
void stage1_mma(const float* __restrict__ x,
                const float* __restrict__ W1, const float* __restrict__ W2,
                const float* __restrict__ b1, const float* __restrict__ b2,
                float* __restrict__ X1, float* __restrict__ X2)
{
    extern __shared__ __align__(16) float gsm[];
    const u32 sb = (u32)__cvta_generic_to_shared(gsm);

    const int t = threadIdx.x;
    const int lane = t & 31, warp = t >> 5;
    const int wm = warp >> 2, wn = warp & 3;
    const int gid = lane >> 2, ctid = lane & 3;
    const int m0 = blockIdx.x * 32;
    const int n0 = blockIdx.y * 64;

    const int arI = t >> 3, ak = (t & 7) * 4;
    const int brI = t >> 3, bk = (t & 7) * 4;
    const float* aG  = x + (size_t)(m0 + arI) * TDIM + ak;
    const int bn1 = n0 + brI, bn2 = n0 + brI + 32;
    const float* bG1 = (bn1 < 128) ? W1 + (size_t)bn1 * TDIM + bk
                                   : W2 + (size_t)(bn1 - 128) * TDIM + bk;
    const float* bG2 = (bn2 < 128) ? W1 + (size_t)bn2 * TDIM + bk
                                   : W2 + (size_t)(bn2 - 128) * TDIM + bk;
    const u32 sA  = sb + (arI * SROW + ak) * 4;
    const u32 sB1 = sb + (ST_A + brI * SROW + bk) * 4;
    const u32 sB2 = sb + (ST_A + (brI + 32) * SROW + bk) * 4;

    Acc3 A3; A3.zero();
    const int nt = TDIM / 32;   // 9

#define S1_ISSUE(ch) do {                                  \
        int kc_ = (ch) * 32;                               \
        u32 so_ = (u32)(((ch) & 3) * ST_SZ * 4);           \
        cpa16(sA  + so_, aG  + kc_);                       \
        cpa16(sB1 + so_, bG1 + kc_);                       \
        cpa16(sB2 + so_, bG2 + kc_);                       \
        cp_commit();                                       \
    } while (0)

    S1_ISSUE(0); S1_ISSUE(1); S1_ISSUE(2);
    for (int ti = 0; ti < nt; ti++) {
        cp_wait<2>();
        __syncthreads();
        if (ti + 3 < nt) S1_ISSUE(ti + 3);
        const float* stg = gsm + (ti & 3) * ST_SZ;
        mma_chunk_cvt(A3, stg, stg + ST_A, wm, wn, gid, ctid);
        __syncthreads();
    }
#undef S1_ISSUE

    const int half = (n0 < 128);
    float* OUT = half ? X1 : X2;
    const float* bias = half ? b1 : b2;
    const int nloc0 = half ? n0 : n0 - 128;
    const int row = m0 + wm * 16 + gid;
#pragma unroll
    for (int nf = 0; nf < 2; nf++) {
        int col = nloc0 + wn * 16 + nf * 8 + 2 * ctid;
        float v0 = A3.get(nf, 0) + bias[col];
        float v1 = A3.get(nf, 1) + bias[col + 1];
        float v2 = A3.get(nf, 2) + bias[col];
        float v3 = A3.get(nf, 3) + bias[col + 1];
        v0 = fmaxf(v0, 0.2f * v0); v1 = fmaxf(v1, 0.2f * v1);
        v2 = fmaxf(v2, 0.2f * v2); v3 = fmaxf(v3, 0.2f * v3);
        *(float2*)&OUT[(size_t)row * LDIM + col]       = make_float2(v0, v1);
        *(float2*)&OUT[(size_t)(row + 8) * LDIM + col] = make_float2(v2, v3);
    }
}

// Stage 2: z=0: S1 = X1 @ Wp_a^T ; z=1: S2P = X2 @ Wp_b^T + bp. grid (64,2,2).
__global__ __launch_bounds__(256)
void stage2_mma(const float* __restrict__ X1, const float* __restrict__ X2,
                const float* __restrict__ Wp, const float* __restrict__ bp,
                float* __restrict__ S1, float* __restrict__ S2P)
{
    extern __shared__ __align__(16) float gsm[];
    const u32 sb = (u32)__cvta_generic_to_shared(gsm);

    const int t = threadIdx.x;
    const int lane = t & 31, warp = t >> 5;
    const int wm = warp >> 2, wn = warp & 3;
    const int gid = lane >> 2, ctid = lane & 3;
    const int m0 = blockIdx.x * 32;
    const int n0 = blockIdx.y * 64;
    const int z  = blockIdx.z;

    const float* A = z ? X2 : X1;
    const int arI = t >> 3, ak = (t & 7) * 4;
    const int brI = t >> 3, bk = (t & 7) * 4;
    const float* aG  = A + (size_t)(m0 + arI) * LDIM + ak;
    const float* bG1 = Wp + (size_t)(n0 + brI) * (2 * LDIM) + z * LDIM + bk;
    const float* bG2 = Wp + (size_t)(n0 + brI + 32) * (2 * LDIM) + z * LDIM + bk;
    const u32 sA  = sb + (arI * SROW + ak) * 4;
    const u32 sB1 = sb + (ST_A + brI * SROW + bk) * 4;
    const u32 sB2 = sb + (ST_A + (brI + 32) * SROW + bk) * 4;

    Acc3 A3; A3.zero();
    const int nt = LDIM / 32;   // 4

#define S2_ISSUE(ch) do {                                  \
        int kc_ = (ch) * 32;                               \
        u32 so_ = (u32)(((ch) & 3) * ST_SZ * 4);           \
        cpa16(sA  + so_, aG  + kc_);                       \
        cpa16(sB1 + so_, bG1 + kc_);                       \
        cpa16(sB2 + so_, bG2 + kc_);                       \
        cp_commit();                                       \
    } while (0)

    S2_ISSUE(0); S2_ISSUE(1); S2_ISSUE(2);
    for (int ti = 0; ti < nt; ti++) {
        cp_wait<2>();
        __syncthreads();
        if (ti + 3 < nt) S2_ISSUE(ti + 3);
        const float* stg = gsm + (ti & 3) * ST_SZ;
        mma_chunk_cvt(A3, stg, stg + ST_A, wm, wn, gid, ctid);
        __syncthreads();
    }
#undef S2_ISSUE

    float* OUT = z ? S2P : S1;
    const int row = m0 + wm * 16 + gid;
#pragma unroll
    for (int nf = 0; nf < 2; nf++) {
        int col = n0 + wn * 16 + nf * 8 + 2 * ctid;
        float bv0 = z ? bp[col] : 0.f;
        float bv1 = z ? bp[col + 1] : 0.f;
        *(float2*)&OUT[(size_t)row * LDIM + col] =
            make_float2(A3.get(nf, 0) + bv0, A3.get(nf, 1) + bv1);
        *(float2*)&OUT[(size_t)(row + 8) * LDIM + col] =
            make_float2(A3.get(nf, 2) + bv0, A3.get(nf, 3) + bv1);
    }
}

// ---------------------------------------------------------------------------
// Pairwise: 64x64 tile per block (one b), grid (8, 8, 4), 256 threads,
// 4x4 u64 micro-tile per thread (low register pressure -> deep pipelining).
// ---------------------------------------------------------------------------
#define SR2 65   // u64 per row (64 + 1 pad)
#define PW_S2   (64 * SR2)          // 4160
#define PW_C1   (2 * 64 * SR2)      // 8320
#define PW_C2   (PW_C1 + 64)        // 8384
#define PW_ROWF ((PW_C2 + 64) * 2)  // float index of rowA = 16896
#define PW_U64_TOTAL (PW_C2 + 64 + 64)  // 8512 u64 = 68,096 bytes

__global__ __launch_bounds__(256)
void pairwise_kernel(const float* __restrict__ S1, const float* __restrict__ S2P,
                     const float* __restrict__ Wb, const float* __restrict__ bb,
                     float* __restrict__ P)
{
    extern __shared__ __align__(16) u64 sm[];
    u64*   s1t  = sm;
    u64*   s2t  = sm + PW_S2;
    u64*   c1   = sm + PW_C1;
    u64*   c2   = sm + PW_C2;
    float* rowA = ((float*)sm) + PW_ROWF;        // [64]
    float* rowB = rowA + 64;                     // [64]

    const int t  = threadIdx.x;
    const int tx = t & 15;          // j micro col 0..15
    const int ty = t >> 4;          // i micro row 0..15
    const int j0 = blockIdx.x * 64;
    const int i0 = blockIdx.y * 64;
    const int b  = blockIdx.z;

    if (t < 64) {
        float2 w = ((const float2*)Wb)[t];
        c1[t] = pack2(0.6f * w.x, 0.6f * w.y);
        c2[t] = pack2(0.4f * w.x, 0.4f * w.y);
    }

    const float4* S1v = (const float4*)(S1  + ((size_t)b * N_NODES + i0) * LDIM);
    const float4* S2v = (const float4*)(S2P + ((size_t)b * N_NODES + j0) * LDIM);
#pragma unroll
    for (int s = 0; s < 8; s++) {
        int f   = t + s * 256;          // 0..2047
        int row = f >> 5;
        int c4  = f & 31;
        float4 v = S1v[row * 32 + c4];
        float4 w = S2v[row * 32 + c4];
        float2* d = (float2*)&s1t[row * SR2 + c4 * 2];
        d[0] = make_float2(v.x, v.y);
        d[1] = make_float2(v.z, v.w);
        float2* e = (float2*)&s2t[row * SR2 + c4 * 2];
        e[0] = make_float2(w.x, w.y);
        e[1] = make_float2(w.z, w.w);
    }
    __syncthreads();

    // separable linear parts: t<128 -> s1 rows (2 thr/row), t>=128 -> s2 rows
    {
        int tt   = t & 127;
        int row  = tt >> 1;
        int half = tt & 1;
        const u64* cc  = c1 + half * 32;
        const u64* src = ((t < 128) ? s1t : s2t) + row * SR2 + half * 32;
        u64 a0 = 0, a1 = 0;
#pragma unroll
        for (int q = 0; q < 32; q += 2) {
            a0 = fma2(cc[q],     src[q],     a0);
            a1 = fma2(cc[q + 1], src[q + 1], a1);
        }
        float s = lo32(a0) + hi32(a0) + lo32(a1) + hi32(a1);
        s += __shfl_xor_sync(0xffffffffu, s, 1);
        if (half == 0) {
            if (t < 128) rowA[row] = s; else rowB[row] = s;
        }
    }
    __syncthreads();

    u64 acc[4][4] = {};
    const u64 MASK = 0x7fffffff7fffffffULL;
#pragma unroll 4
    for (int kk = 0; kk < 64; kk++) {
        u64 cw = c2[kk];
        u64 ra[4], rb[4];
#pragma unroll
        for (int r = 0; r < 4; r++) ra[r] = s1t[(ty + 16 * r) * SR2 + kk];
#pragma unroll
        for (int c = 0; c < 4; c++) rb[c] = s2t[(tx + 16 * c) * SR2 + kk];
#pragma unroll
        for (int r = 0; r < 4; r++)
#pragma unroll
            for (int c = 0; c < 4; c++) {
                u64 v = add2(ra[r], rb[c]);
                acc[r][c] = fma2(cw, v & MASK, acc[r][c]);
            }
    }

    const float bbv = bb[0];
    float* Pb = P + (size_t)b * N_NODES * N_NODES;
#pragma unroll
    for (int r = 0; r < 4; r++) {
        int i = i0 + ty + 16 * r;
        float ai = rowA[ty + 16 * r] + bbv;
#pragma unroll
        for (int c = 0; c < 4; c++) {
            int j = j0 + tx + 16 * c;
            float z = lo32(acc[r][c]) + hi32(acc[r][c])
                    + ai + rowB[tx + 16 * c];
            Pb[(size_t)i * N_NODES + j] = 1.f / (1.f + __expf(-z));
        }
    }
}

// ---------------------------------------------------------------------------
// Finalize: p = mean_b P -> diag mask -> clamped logit -> +logistic(noise)
//           -> sigmoid(/0.2). One float4 per thread.
// ---------------------------------------------------------------------------
__global__ __launch_bounds__(128)
void finalize_kernel(const float* __restrict__ P, const float* __restrict__ noise,
                     float* __restrict__ out)
{
    int q = blockIdx.x * 128 + threadIdx.x;   // float4 index
    const int PL4 = N_NODES * N_NODES / 4;
    float4 p0 = ((const float4*)P)[q];
    float4 p1 = ((const float4*)P)[q + PL4];
    float4 p2 = ((const float4*)P)[q + 2 * PL4];
    float4 p3 = ((const float4*)P)[q + 3 * PL4];
    float4 ns = ((const float4*)noise)[q];

    int idx0 = q * 4;
    int i = idx0 >> 9;
    int jbase = idx0 & (N_NODES - 1);

    float pv[4] = { 0.25f * (p0.x + p1.x + p2.x + p3.x),
                    0.25f * (p0.y + p1.y + p2.y + p3.y),
                    0.25f * (p0.z + p1.z + p2.z + p3.z),
                    0.25f * (p0.w + p1.w + p2.w + p3.w) };
    float nv[4] = { ns.x, ns.y, ns.z, ns.w };
    float4 o;
    float* op = (float*)&o;
#pragma unroll
    for (int e = 0; e < 4; e++) {
        float p = pv[e];
        if (i == jbase + e) p = 0.f;
        float lp = __logf(p + 1e-10f) - __logf(1.0f + (1e-10f - p));
        lp = fminf(fmaxf(lp, -10.f), 10.f);
        float lo = __logf(nv[e]) - __logf(1.0f - nv[e]);
        float z = (lp + lo) * 5.0f;     // / TEMPERATURE (0.2)
        op[e] = 1.f / (1.f + __expf(-z));
    }
    ((float4*)out)[q] = o;
}

// ---------------------------------------------------------------------------
extern "C" void kernel_launch(void* const* d_in, const int* in_sizes, int n_in,
                              void* d_out, int out_size)
{
    const float* x     = (const float*)d_in[0];
    const float* W1    = (const float*)d_in[1];
    const float* b1    = (const float*)d_in[2];
    const float* W2    = (const float*)d_in[3];
    const float* b2    = (const float*)d_in[4];
    const float* Wp    = (const float*)d_in[5];
    const float* bp    = (const float*)d_in[6];
    const float* Wb    = (const float*)d_in[7];
    const float* bb    = (const float*)d_in[8];
    const float* noise = (const float*)d_in[9];
    float* out = (float*)d_out;

    float *X1, *X2, *S1, *S2P, *P;
    cudaGetSymbolAddress((void**)&X1,  g_X1);
    cudaGetSymbolAddress((void**)&X2,  g_X2);
    cudaGetSymbolAddress((void**)&S1,  g_S1);
    cudaGetSymbolAddress((void**)&S2P, g_S2P);
    cudaGetSymbolAddress((void**)&P,   g_P);

    const size_t gemm_smem = (size_t)GEMM_SMEM_FLOATS * sizeof(float);  // 55296 B
    cudaFuncSetAttribute(stage1_mma, cudaFuncAttributeMaxDynamicSharedMemorySize,
                         (int)gemm_smem);
    cudaFuncSetAttribute(stage2_mma, cudaFuncAttributeMaxDynamicSharedMemorySize,
                         (int)gemm_smem);

    // Stage 1: [X1|X2] = leaky(x @ [W1;W2]^T + bias)
    stage1_mma<<<dim3(MROWS / 32, 4), 256, gemm_smem>>>(x, W1, W2, b1, b2, X1, X2);

    // Stage 2: S1 = X1@Wp_a^T, S2P = X2@Wp_b^T + bp
    stage2_mma<<<dim3(MROWS / 32, 2, 2), 256, gemm_smem>>>(X1, X2, Wp, bp, S1, S2P);

    // Stage 3: pairwise sigmoid planes (64x64 tiles, 256 threads, one b/block)
    size_t pw_smem = (size_t)PW_U64_TOTAL * sizeof(u64);   // 68,096 B
    cudaFuncSetAttribute(pairwise_kernel,
                         cudaFuncAttributeMaxDynamicSharedMemorySize, (int)pw_smem);
    dim3 g3(N_NODES / 64, N_NODES / 64, BBATCH);   // 8 x 8 x 4 = 256
    pairwise_kernel<<<g3, dim3(256), pw_smem>>>(S1, S2P, Wb, bb, P);

    // Stage 4: epilogue
    finalize_kernel<<<N_NODES * N_NODES / 4 / 128, 128>>>(P, noise, out);
}

// round 15
// speedup vs baseline: 1.0414x; 1.0108x over previous
#include <cuda_runtime.h>
#include <math.h>

#define N_NODES 512
#define TDIM 288
#define LDIM 128
#define BBATCH 4
#define MROWS (BBATCH * N_NODES)   // 2048

typedef unsigned long long u64;
typedef unsigned int u32;

// ---- packed f32x2 helpers (sm_100+) ----
__device__ __forceinline__ u64 add2(u64 a, u64 b) {
    u64 r; asm("add.rn.f32x2 %0,%1,%2;" : "=l"(r) : "l"(a), "l"(b)); return r;
}
__device__ __forceinline__ u64 fma2(u64 a, u64 b, u64 c) {
    u64 r; asm("fma.rn.f32x2 %0,%1,%2,%3;" : "=l"(r) : "l"(a), "l"(b), "l"(c)); return r;
}
__device__ __forceinline__ float lo32(u64 v) { return __uint_as_float((unsigned)(v & 0xffffffffu)); }
__device__ __forceinline__ float hi32(u64 v) { return __uint_as_float((unsigned)(v >> 32)); }
__device__ __forceinline__ u64 pack2(float x, float y) {
    return ((u64)__float_as_uint(y) << 32) | (u64)__float_as_uint(x);
}

// ---- tf32 helpers ----
__device__ __forceinline__ u32 tf32_bits(float v) {
    u32 r; asm("cvt.rna.tf32.f32 %0,%1;" : "=r"(r) : "f"(v));
    return r;
}
__device__ __forceinline__ void mma_tf32(float* d, const u32* a, const u32* b) {
    asm("mma.sync.aligned.m16n8k8.row.col.f32.tf32.tf32.f32 "
        "{%0,%1,%2,%3}, {%4,%5,%6,%7}, {%8,%9}, {%0,%1,%2,%3};"
        : "+f"(d[0]), "+f"(d[1]), "+f"(d[2]), "+f"(d[3])
        : "r"(a[0]), "r"(a[1]), "r"(a[2]), "r"(a[3]), "r"(b[0]), "r"(b[1]));
}

// ---- cp.async helpers ----
__device__ __forceinline__ void cpa16(u32 s, const void* g) {
    asm volatile("cp.async.ca.shared.global [%0], [%1], 16;" :: "r"(s), "l"(g));
}
__device__ __forceinline__ void cp_commit() {
    asm volatile("cp.async.commit_group;");
}
template <int N> __device__ __forceinline__ void cp_wait() {
    asm volatile("cp.async.wait_group %0;" :: "n"(N));
}

// ---- MUFU-free math ----
// Newton reciprocal: bit-trick seed + 3 iterations (rel err ~1e-9).
// Valid for normal positive a (including very large); NOT for inf.
__device__ __forceinline__ float rcp_nt(float a) {
    float y = __int_as_float(0x7EF477D5 - __float_as_int(a));
    y = y * fmaf(-a, y, 2.0f);
    y = y * fmaf(-a, y, 2.0f);
    y = y * fmaf(-a, y, 2.0f);
    return y;
}
// sigmoid via 2^t polynomial (deg 6, rel err ~1e-7) + Newton rcp. Zero MUFU.
__device__ __forceinline__ float sigmoid_fma(float z) {
    float t = fmaf(z, -1.4426950408889634f, 0.0f);   // -z*log2(e)
    t = fminf(fmaxf(t, -100.f), 100.f);
    int ii = __float2int_rn(t);
    float f = t - (float)ii;                          // f in [-0.5, 0.5]
    float p = 1.5403530e-4f;
    p = fmaf(p, f, 1.3333558e-3f);
    p = fmaf(p, f, 9.6181291e-3f);
    p = fmaf(p, f, 5.5504109e-2f);
    p = fmaf(p, f, 2.4022651e-1f);
    p = fmaf(p, f, 6.9314718e-1f);
    p = fmaf(p, f, 1.0f);
    float e = p * __int_as_float((ii + 127) << 23);   // e^{-z}
    return rcp_nt(1.0f + e);
}

// Scratch (device globals)
__device__ float g_X1[MROWS * LDIM];
__device__ float g_X2[MROWS * LDIM];
__device__ float g_S1[MROWS * LDIM];
__device__ float g_S2P[MROWS * LDIM];
__device__ float g_P[BBATCH * N_NODES * N_NODES];

// ---------------------------------------------------------------------------
// GEMM core (R14 — proven): BM=32, BN=64, BK=32, 8 warps, 4-stage cp.async
// ring, tf32 split in registers, 3 independent accumulator sets.
// ---------------------------------------------------------------------------
#define SROW 36
#define ST_A (32 * SROW)
#define ST_B (64 * SROW)
#define ST_SZ (ST_A + ST_B)
#define NSTAGE 4
#define GEMM_SMEM_FLOATS (NSTAGE * ST_SZ)   // 55296 B

__device__ __forceinline__ void split1(float v, u32& h, u32& l) {
    h = tf32_bits(v);
    l = tf32_bits(v - __uint_as_float(h));
}

struct Acc3 {
    float hh[2][4], hl[2][4], lh[2][4];
    __device__ __forceinline__ void zero() {
#pragma unroll
        for (int nf = 0; nf < 2; nf++)
#pragma unroll
            for (int e = 0; e < 4; e++) {
                hh[nf][e] = 0.f; hl[nf][e] = 0.f; lh[nf][e] = 0.f;
            }
    }
    __device__ __forceinline__ float get(int nf, int e) const {
        return hh[nf][e] + (hl[nf][e] + lh[nf][e]);
    }
};

__device__ __forceinline__ void mma_chunk_cvt(Acc3& A3,
                                              const float* SA, const float* SB,
                                              int wm, int wn, int gid, int ctid) {
    const int ar0 = (wm * 16 + gid) * SROW;
    const int ar1 = (wm * 16 + gid + 8) * SROW;
#pragma unroll
    for (int kk = 0; kk < 4; kk++) {
        int k8 = kk * 8;
        float av[4], bv[2][2];
        av[0] = SA[ar0 + k8 + ctid];
        av[1] = SA[ar1 + k8 + ctid];
        av[2] = SA[ar0 + k8 + ctid + 4];
        av[3] = SA[ar1 + k8 + ctid + 4];
#pragma unroll
        for (int nf = 0; nf < 2; nf++) {
            int r = (wn * 16 + nf * 8 + gid) * SROW;
            bv[nf][0] = SB[r + k8 + ctid];
            bv[nf][1] = SB[r + k8 + ctid + 4];
        }
        u32 ah[4], al[4], bh[2][2], bl[2][2];
#pragma unroll
        for (int i = 0; i < 4; i++) split1(av[i], ah[i], al[i]);
#pragma unroll
        for (int nf = 0; nf < 2; nf++) {
            split1(bv[nf][0], bh[nf][0], bl[nf][0]);
            split1(bv[nf][1], bh[nf][1], bl[nf][1]);
        }
#pragma unroll
        for (int nf = 0; nf < 2; nf++) {
            mma_tf32(A3.hh[nf], ah, bh[nf]);
            mma_tf32(A3.hl[nf], ah, bl[nf]);
            mma_tf32(A3.lh[nf], al, bh[nf]);
        }
    }
}

// Stage 1: [X1|X2] = leaky(x @ [W1;W2]^T + bias). grid (64, 4).
__global__ __launch_bounds__(256)
void stage1_mma(const float* __restrict__ x,
                const float* __restrict__ W1, const float* __restrict__ W2,
                const float* __restrict__ b1, const float* __restrict__ b2,
                float* __restrict__ X1, float* __restrict__ X2)
{
    extern __shared__ __align__(16) float gsm[];
    const u32 sb = (u32)__cvta_generic_to_shared(gsm);

    const int t = threadIdx.x;
    const int lane = t & 31, warp = t >> 5;
    const int wm = warp >> 2, wn = warp & 3;
    const int gid = lane >> 2, ctid = lane & 3;
    const int m0 = blockIdx.x * 32;
    const int n0 = blockIdx.y * 64;

    const int arI = t >> 3, ak = (t & 7) * 4;
    const int brI = t >> 3, bk = (t & 7) * 4;
    const float* aG  = x + (size_t)(m0 + arI) * TDIM + ak;
    const int bn1 = n0 + brI, bn2 = n0 + brI + 32;
    const float* bG1 = (bn1 < 128) ? W1 + (size_t)bn1 * TDIM + bk
                                   : W2 + (size_t)(bn1 - 128) * TDIM + bk;
    const float* bG2 = (bn2 < 128) ? W1 + (size_t)bn2 * TDIM + bk
                                   : W2 + (size_t)(bn2 - 128) * TDIM + bk;
    const u32 sA  = sb + (arI * SROW + ak) * 4;
    const u32 sB1 = sb + (ST_A + brI * SROW + bk) * 4;
    const u32 sB2 = sb + (ST_A + (brI + 32) * SROW + bk) * 4;

    Acc3 A3; A3.zero();
    const int nt = TDIM / 32;   // 9

#define S1_ISSUE(ch) do {                                  \
        int kc_ = (ch) * 32;                               \
        u32 so_ = (u32)(((ch) & 3) * ST_SZ * 4);           \
        cpa16(sA  + so_, aG  + kc_);                       \
        cpa16(sB1 + so_, bG1 + kc_);                       \
        cpa16(sB2 + so_, bG2 + kc_);                       \
        cp_commit();                                       \
    } while (0)

    S1_ISSUE(0); S1_ISSUE(1); S1_ISSUE(2);
    for (int ti = 0; ti < nt; ti++) {
        cp_wait<2>();
        __syncthreads();
        if (ti + 3 < nt) S1_ISSUE(ti + 3);
        const float* stg = gsm + (ti & 3) * ST_SZ;
        mma_chunk_cvt(A3, stg, stg + ST_A, wm, wn, gid, ctid);
        __syncthreads();
    }
#undef S1_ISSUE

    const int half = (n0 < 128);
    float* OUT = half ? X1 : X2;
    const float* bias = half ? b1 : b2;
    const int nloc0 = half ? n0 : n0 - 128;
    const int row = m0 + wm * 16 + gid;
#pragma unroll
    for (int nf = 0; nf < 2; nf++) {
        int col = nloc0 + wn * 16 + nf * 8 + 2 * ctid;
        float v0 = A3.get(nf, 0) + bias[col];
        float v1 = A3.get(nf, 1) + bias[col + 1];
        float v2 = A3.get(nf, 2) + bias[col];
        float v3 = A3.get(nf, 3) + bias[col + 1];
        v0 = fmaxf(v0, 0.2f * v0); v1 = fmaxf(v1, 0.2f * v1);
        v2 = fmaxf(v2, 0.2f * v2); v3 = fmaxf(v3, 0.2f * v3);
        *(float2*)&OUT[(size_t)row * LDIM + col]       = make_float2(v0, v1);
        *(float2*)&OUT[(size_t)(row + 8) * LDIM + col] = make_float2(v2, v3);
    }
}

// Stage 2: z=0: S1 = X1 @ Wp_a^T ; z=1: S2P = X2 @ Wp_b^T + bp. grid (64,2,2).
__global__ __launch_bounds__(256)
void stage2_mma(const float* __restrict__ X1, const float* __restrict__ X2,
                const float* __restrict__ Wp, const float* __restrict__ bp,
                float* __restrict__ S1, float* __restrict__ S2P)
{
    extern __shared__ __align__(16) float gsm[];
    const u32 sb = (u32)__cvta_generic_to_shared(gsm);

    const int t = threadIdx.x;
    const int lane = t & 31, warp = t >> 5;
    const int wm = warp >> 2, wn = warp & 3;
    const int gid = lane >> 2, ctid = lane & 3;
    const int m0 = blockIdx.x * 32;
    const int n0 = blockIdx.y * 64;
    const int z  = blockIdx.z;

    const float* A = z ? X2 : X1;
    const int arI = t >> 3, ak = (t & 7) * 4;
    const int brI = t >> 3, bk = (t & 7) * 4;
    const float* aG  = A + (size_t)(m0 + arI) * LDIM + ak;
    const float* bG1 = Wp + (size_t)(n0 + brI) * (2 * LDIM) + z * LDIM + bk;
    const float* bG2 = Wp + (size_t)(n0 + brI + 32) * (2 * LDIM) + z * LDIM + bk;
    const u32 sA  = sb + (arI * SROW + ak) * 4;
    const u32 sB1 = sb + (ST_A + brI * SROW + bk) * 4;
    const u32 sB2 = sb + (ST_A + (brI + 32) * SROW + bk) * 4;

    Acc3 A3; A3.zero();
    const int nt = LDIM / 32;   // 4

#define S2_ISSUE(ch) do {                                  \
        int kc_ = (ch) * 32;                               \
        u32 so_ = (u32)(((ch) & 3) * ST_SZ * 4);           \
        cpa16(sA  + so_, aG  + kc_);                       \
        cpa16(sB1 + so_, bG1 + kc_);                       \
        cpa16(sB2 + so_, bG2 + kc_);                       \
        cp_commit();                                       \
    } while (0)

    S2_ISSUE(0); S2_ISSUE(1); S2_ISSUE(2);
    for (int ti = 0; ti < nt; ti++) {
        cp_wait<2>();
        __syncthreads();
        if (ti + 3 < nt) S2_ISSUE(ti + 3);
        const float* stg = gsm + (ti & 3) * ST_SZ;
        mma_chunk_cvt(A3, stg, stg + ST_A, wm, wn, gid, ctid);
        __syncthreads();
    }
#undef S2_ISSUE

    float* OUT = z ? S2P : S1;
    const int row = m0 + wm * 16 + gid;
#pragma unroll
    for (int nf = 0; nf < 2; nf++) {
        int col = n0 + wn * 16 + nf * 8 + 2 * ctid;
        float bv0 = z ? bp[col] : 0.f;
        float bv1 = z ? bp[col + 1] : 0.f;
        *(float2*)&OUT[(size_t)row * LDIM + col] =
            make_float2(A3.get(nf, 0) + bv0, A3.get(nf, 1) + bv1);
        *(float2*)&OUT[(size_t)(row + 8) * LDIM + col] =
            make_float2(A3.get(nf, 2) + bv0, A3.get(nf, 3) + bv1);
    }
}

// ---------------------------------------------------------------------------
// Pairwise: 64x64 tile per block (one b), grid (8, 8, 4), 256 threads,
// 4x4 u64 micro-tile. Sigmoid is MUFU-free (poly exp2 + Newton rcp).
// ---------------------------------------------------------------------------
#define SR2 65   // u64 per row (64 + 1 pad)
#define PW_S2   (64 * SR2)          // 4160
#define PW_C1   (2 * 64 * SR2)      // 8320
#define PW_C2   (PW_C1 + 64)        // 8384
#define PW_ROWF ((PW_C2 + 64) * 2)  // float index of rowA = 16896
#define PW_U64_TOTAL (PW_C2 + 64 + 64)  // 8512 u64 = 68,096 bytes

__global__ __launch_bounds__(256)
void pairwise_kernel(const float* __restrict__ S1, const float* __restrict__ S2P,
                     const float* __restrict__ Wb, const float* __restrict__ bb,
                     float* __restrict__ P)
{
    extern __shared__ __align__(16) u64 sm[];
    u64*   s1t  = sm;
    u64*   s2t  = sm + PW_S2;
    u64*   c1   = sm + PW_C1;
    u64*   c2   = sm + PW_C2;
    float* rowA = ((float*)sm) + PW_ROWF;        // [64]
    float* rowB = rowA + 64;                     // [64]

    const int t  = threadIdx.x;
    const int tx = t & 15;          // j micro col 0..15
    const int ty = t >> 4;          // i micro row 0..15
    const int j0 = blockIdx.x * 64;
    const int i0 = blockIdx.y * 64;
    const int b  = blockIdx.z;

    if (t < 64) {
        float2 w = ((const float2*)Wb)[t];
        c1[t] = pack2(0.6f * w.x, 0.6f * w.y);
        c2[t] = pack2(0.4f * w.x, 0.4f * w.y);
    }

    const float4* S1v = (const float4*)(S1  + ((size_t)b * N_NODES + i0) * LDIM);
    const float4* S2v = (const float4*)(S2P + ((size_t)b * N_NODES + j0) * LDIM);
#pragma unroll
    for (int s = 0; s < 8; s++) {
        int f   = t + s * 256;          // 0..2047
        int row = f >> 5;
        int c4  = f & 31;
        float4 v = S1v[row * 32 + c4];
        float4 w = S2v[row * 32 + c4];
        float2* d = (float2*)&s1t[row * SR2 + c4 * 2];
        d[0] = make_float2(v.x, v.y);
        d[1] = make_float2(v.z, v.w);
        float2* e = (float2*)&s2t[row * SR2 + c4 * 2];
        e[0] = make_float2(w.x, w.y);
        e[1] = make_float2(w.z, w.w);
    }
    __syncthreads();

    // separable linear parts: t<128 -> s1 rows (2 thr/row), t>=128 -> s2 rows
    {
        int tt   = t & 127;
        int row  = tt >> 1;
        int half = tt & 1;
        const u64* cc  = c1 + half * 32;
        const u64* src = ((t < 128) ? s1t : s2t) + row * SR2 + half * 32;
        u64 a0 = 0, a1 = 0;
#pragma unroll
        for (int q = 0; q < 32; q += 2) {
            a0 = fma2(cc[q],     src[q],     a0);
            a1 = fma2(cc[q + 1], src[q + 1], a1);
        }
        float s = lo32(a0) + hi32(a0) + lo32(a1) + hi32(a1);
        s += __shfl_xor_sync(0xffffffffu, s, 1);
        if (half == 0) {
            if (t < 128) rowA[row] = s; else rowB[row] = s;
        }
    }
    __syncthreads();

    u64 acc[4][4] = {};
    const u64 MASK = 0x7fffffff7fffffffULL;
#pragma unroll 4
    for (int kk = 0; kk < 64; kk++) {
        u64 cw = c2[kk];
        u64 ra[4], rb[4];
#pragma unroll
        for (int r = 0; r < 4; r++) ra[r] = s1t[(ty + 16 * r) * SR2 + kk];
#pragma unroll
        for (int c = 0; c < 4; c++) rb[c] = s2t[(tx + 16 * c) * SR2 + kk];
#pragma unroll
        for (int r = 0; r < 4; r++)
#pragma unroll
            for (int c = 0; c < 4; c++) {
                u64 v = add2(ra[r], rb[c]);
                acc[r][c] = fma2(cw, v & MASK, acc[r][c]);
            }
    }

    const float bbv = bb[0];
    float* Pb = P + (size_t)b * N_NODES * N_NODES;
#pragma unroll
    for (int r = 0; r < 4; r++) {
        int i = i0 + ty + 16 * r;
        float ai = rowA[ty + 16 * r] + bbv;
#pragma unroll
        for (int c = 0; c < 4; c++) {
            int j = j0 + tx + 16 * c;
            float z = lo32(acc[r][c]) + hi32(acc[r][c])
                    + ai + rowB[tx + 16 * c];
            Pb[(size_t)i * N_NODES + j] = sigmoid_fma(z);
        }
    }
}

// ---------------------------------------------------------------------------
// Finalize (MUFU-free): out = 1/(1 + R^-5),
//   R = clamp((p+eps)/(1-p+eps), e^-10, e^10) * ns/(1-ns)
// Exact rewrite of sigmoid((clamp(logit_p)+logistic)/0.2) since 1/T = 5.
// ---------------------------------------------------------------------------
__global__ __launch_bounds__(128)
void finalize_kernel(const float* __restrict__ P, const float* __restrict__ noise,
                     float* __restrict__ out)
{
    int q = blockIdx.x * 128 + threadIdx.x;   // float4 index
    const int PL4 = N_NODES * N_NODES / 4;
    float4 p0 = ((const float4*)P)[q];
    float4 p1 = ((const float4*)P)[q + PL4];
    float4 p2 = ((const float4*)P)[q + 2 * PL4];
    float4 p3 = ((const float4*)P)[q + 3 * PL4];
    float4 ns = ((const float4*)noise)[q];

    int idx0 = q * 4;
    int i = idx0 >> 9;
    int jbase = idx0 & (N_NODES - 1);

    float pv[4] = { 0.25f * (p0.x + p1.x + p2.x + p3.x),
                    0.25f * (p0.y + p1.y + p2.y + p3.y),
                    0.25f * (p0.z + p1.z + p2.z + p3.z),
                    0.25f * (p0.w + p1.w + p2.w + p3.w) };
    float nv[4] = { ns.x, ns.y, ns.z, ns.w };
    float4 o;
    float* op = (float*)&o;
#pragma unroll
    for (int e = 0; e < 4; e++) {
        float p = pv[e];
        if (i == jbase + e) p = 0.f;
        // r1 = (p+eps)/(1-p+eps), clamped to [e^-10, e^10]
        float r1 = (p + 1e-10f) * rcp_nt(1.0f + (1e-10f - p));
        r1 = fminf(fmaxf(r1, 4.5399930e-5f), 22026.466f);
        // invR = (1-ns)/(r1*ns)
        float invR = (1.0f - nv[e]) * rcp_nt(r1 * nv[e]);
        // t = invR^5 (clamped so 1+t stays finite for Newton rcp)
        float i2 = invR * invR;
        float tpw = fminf(i2 * i2 * invR, 1e30f);
        op[e] = rcp_nt(1.0f + tpw);
    }
    ((float4*)out)[q] = o;
}

// ---------------------------------------------------------------------------
extern "C" void kernel_launch(void* const* d_in, const int* in_sizes, int n_in,
                              void* d_out, int out_size)
{
    const float* x     = (const float*)d_in[0];
    const float* W1    = (const float*)d_in[1];
    const float* b1    = (const float*)d_in[2];
    const float* W2    = (const float*)d_in[3];
    const float* b2    = (const float*)d_in[4];
    const float* Wp    = (const float*)d_in[5];
    const float* bp    = (const float*)d_in[6];
    const float* Wb    = (const float*)d_in[7];
    const float* bb    = (const float*)d_in[8];
    const float* noise = (const float*)d_in[9];
    float* out = (float*)d_out;

    float *X1, *X2, *S1, *S2P, *P;
    cudaGetSymbolAddress((void**)&X1,  g_X1);
    cudaGetSymbolAddress((void**)&X2,  g_X2);
    cudaGetSymbolAddress((void**)&S1,  g_S1);
    cudaGetSymbolAddress((void**)&S2P, g_S2P);
    cudaGetSymbolAddress((void**)&P,   g_P);

    const size_t gemm_smem = (size_t)GEMM_SMEM_FLOATS * sizeof(float);  // 55296 B
    cudaFuncSetAttribute(stage1_mma, cudaFuncAttributeMaxDynamicSharedMemorySize,
                         (int)gemm_smem);
    cudaFuncSetAttribute(stage2_mma, cudaFuncAttributeMaxDynamicSharedMemorySize,
                         (int)gemm_smem);

    // Stage 1: [X1|X2] = leaky(x @ [W1;W2]^T + bias)
    stage1_mma<<<dim3(MROWS / 32, 4), 256, gemm_smem>>>(x, W1, W2, b1, b2, X1, X2);

    // Stage 2: S1 = X1@Wp_a^T, S2P = X2@Wp_b^T + bp
    stage2_mma<<<dim3(MROWS / 32, 2, 2), 256, gemm_smem>>>(X1, X2, Wp, bp, S1, S2P);

    // Stage 3: pairwise sigmoid planes (64x64 tiles, 256 threads, one b/block)
    size_t pw_smem = (size_t)PW_U64_TOTAL * sizeof(u64);   // 68,096 B
    cudaFuncSetAttribute(pairwise_kernel,
                         cudaFuncAttributeMaxDynamicSharedMemorySize, (int)pw_smem);
    dim3 g3(N_NODES / 64, N_NODES / 64, BBATCH);   // 8 x 8 x 4 = 256
    pairwise_kernel<<<g3, dim3(256), pw_smem>>>(S1, S2P, Wb, bb, P);

    // Stage 4: epilogue
    finalize_kernel<<<N_NODES * N_NODES / 4 / 128, 128>>>(P, noise, out);
}